// round 14
// baseline (speedup 1.0000x reference)
#include <cuda_runtime.h>
#include <math.h>

#define B_   16
#define L_   1534
#define C_   16
#define SZ_  512
#define O1_  1023
#define O2_  512
#define EPS_ 1e-3f

__device__ __align__(16) float g_h1b[B_ * 1024];   // h1: [b][o] (o=1023 slot = 0)
__device__ __align__(16) float g_uL[1024];   // uL[j] = sum_o Wl[o]*W2[o][j-o]
__device__ __align__(16) float g_uS[1024];
__device__ float g_const[2];                 // constL, constS

__device__ __forceinline__ void fma2(unsigned long long& d,
                                     unsigned long long a,
                                     unsigned long long b) {
    asm("fma.rn.f32x2 %0, %1, %2, %0;" : "+l"(d) : "l"(a), "l"(b));
}
__device__ __forceinline__ float2 unpack2(unsigned long long v) {
    float2 r;
    asm("mov.b64 {%0, %1}, %2;" : "=f"(r.x), "=f"(r.y) : "l"(v));
    return r;
}

// ---------------------------------------------------------------------------
// K1: 144 blocks.
//   bid 0..127 : stage1 (proven R6 core): h1 = elu(local matmul), now stored
//                as [b][o] (coalesced for K2's gate dot); o=1023 slot zeroed.
//   bid 128..143: gate-weight precompute uL/uS (weights-only, hidden).
// ---------------------------------------------------------------------------
__global__ void __launch_bounds__(256) k_stage1_prep(
        const float* __restrict__ x,  const float* __restrict__ W1,
        const float* __restrict__ b1, const float* __restrict__ W2,
        const float* __restrict__ b2, const float* __restrict__ Wl,
        const float* __restrict__ bl, const float* __restrict__ Ws,
        const float* __restrict__ bs) {
    const int t    = threadIdx.x;
    const int bid  = blockIdx.x;
    const int lane = t & 31;
    const int warp = t >> 5;

    if (bid >= 128) {
        // ================= PREP: u vectors =================
        const int ch = bid - 128;        // 0..15
        const int j0 = ch * 64;
        const int jl = t & 63;
        const int op = t >> 6;
        const int j  = j0 + jl;

        float aL = 0.f, aS = 0.f;
        for (int o = op; o < SZ_; o += 4) {
            int s = j - o;
            if (0 <= s && s < SZ_) {
                float w = W2[o * SZ_ + s];
                aL = fmaf(Wl[o], w, aL);
                aS = fmaf(Ws[o], w, aS);
            }
        }
        __shared__ float sL[4][64], sS[4][64];
        sL[op][jl] = aL;
        sS[op][jl] = aS;
        __syncthreads();
        if (t < 64) {
            g_uL[j0 + t] = sL[0][t] + sL[1][t] + sL[2][t] + sL[3][t];
            g_uS[j0 + t] = sS[0][t] + sS[1][t] + sS[2][t] + sS[3][t];
        }
        if (ch == 0 && warp == 3) {
            float cL = 0.f, cS = 0.f;
            for (int o = lane; o < SZ_; o += 32) {
                float bv = b2[o];
                cL = fmaf(Wl[o], bv, cL);
                cS = fmaf(Ws[o], bv, cS);
            }
#pragma unroll
            for (int off = 16; off; off >>= 1) {
                cL += __shfl_down_sync(0xffffffffu, cL, off);
                cS += __shfl_down_sync(0xffffffffu, cS, off);
            }
            if (lane == 0) {
                g_const[0] = bl[0] + cL;
                g_const[1] = bs[0] + cS;
            }
        }
        return;
    }

    // ================= STAGE 1 (proven R6 core) =================
    const int cq   = lane & 3;
    const int rp   = lane >> 2;
    const int bq   = warp & 3;
    const int kh   = warp >> 2;
    const int o0   = bid * 8;
    const bool full = (o0 + 8 <= O1_);

    unsigned long long acc[8][4];
#pragma unroll
    for (int o = 0; o < 8; o++)
#pragma unroll
        for (int i = 0; i < 4; i++) acc[o][i] = 0ull;

    const int k_begin = kh ? 32 : 0;

    const float* px[4];
#pragma unroll
    for (int i = 0; i < 4; i++)
        px[i] = x + ((4 * bq + i) * L_ + o0 + rp) * 16 + 4 * cq + k_begin * 128;
    const float* pw = W1 + o0 * (SZ_ * C_) + rp * 16 + 4 * cq + k_begin * 128;

    // ---- prologue (kh=0 only), k=0, d=rp: valid o <= rp ----
    if (kh == 0) {
        ulonglong2 xv[4];
#pragma unroll
        for (int i = 0; i < 4; i++) xv[i] = *(const ulonglong2*)px[i];
#pragma unroll
        for (int o = 0; o < 8; o++) {
            if (o <= rp && (full || o0 + o < O1_)) {
                ulonglong2 wv = *(const ulonglong2*)(pw + o * 8176);
#pragma unroll
                for (int i = 0; i < 4; i++) {
                    fma2(acc[o][i], wv.x, xv[i].x);
                    fma2(acc[o][i], wv.y, xv[i].y);
                }
            }
        }
#pragma unroll
        for (int i = 0; i < 4; i++) px[i] += 128;
        pw += 128;
    }

    // ---- interior, software-pipelined double buffer ----
    const int kcount = kh ? 32 : 31;

    ulonglong2 xv[2][4], wv[2][8];
#pragma unroll
    for (int i = 0; i < 4; i++) xv[0][i] = *(const ulonglong2*)px[i];
#pragma unroll
    for (int o = 0; o < 8; o++) wv[0][o] = *(const ulonglong2*)(pw + o * 8176);
#pragma unroll
    for (int i = 0; i < 4; i++) px[i] += 128;
    pw += 128;

    if (full) {
#pragma unroll 2
        for (int k = 0; k < kcount; k++) {
            const int cur = k & 1, nxt = cur ^ 1;
            if (k + 1 < kcount) {
#pragma unroll
                for (int i = 0; i < 4; i++) xv[nxt][i] = *(const ulonglong2*)px[i];
#pragma unroll
                for (int o = 0; o < 8; o++) wv[nxt][o] = *(const ulonglong2*)(pw + o * 8176);
#pragma unroll
                for (int i = 0; i < 4; i++) px[i] += 128;
                pw += 128;
            }
#pragma unroll
            for (int o = 0; o < 8; o++)
#pragma unroll
                for (int i = 0; i < 4; i++) {
                    fma2(acc[o][i], wv[cur][o].x, xv[cur][i].x);
                    fma2(acc[o][i], wv[cur][o].y, xv[cur][i].y);
                }
        }
    } else {
#pragma unroll 2
        for (int k = 0; k < kcount; k++) {
            const int cur = k & 1, nxt = cur ^ 1;
            if (k + 1 < kcount) {
#pragma unroll
                for (int i = 0; i < 4; i++) xv[nxt][i] = *(const ulonglong2*)px[i];
#pragma unroll
                for (int o = 0; o < 8; o++)
                    if (o0 + o < O1_) wv[nxt][o] = *(const ulonglong2*)(pw + o * 8176);
#pragma unroll
                for (int i = 0; i < 4; i++) px[i] += 128;
                pw += 128;
            }
#pragma unroll
            for (int o = 0; o < 8; o++) {
                if (o0 + o < O1_) {
#pragma unroll
                    for (int i = 0; i < 4; i++) {
                        fma2(acc[o][i], wv[cur][o].x, xv[cur][i].x);
                        fma2(acc[o][i], wv[cur][o].y, xv[cur][i].y);
                    }
                }
            }
        }
    }

    // ---- epilogue (kh=1 only), k=64, d=512+rp: valid o > rp ----
    if (kh == 1) {
        int row = o0 + 512 + rp;
        if (row > L_ - 1) row = L_ - 1;     // clamped slots only hit masked o's
        ulonglong2 exv[4];
#pragma unroll
        for (int i = 0; i < 4; i++)
            exv[i] = *(const ulonglong2*)(x + ((4 * bq + i) * L_ + row) * 16 + 4 * cq);
#pragma unroll
        for (int o = 0; o < 8; o++) {
            if (o > rp && (full || o0 + o < O1_)) {
                ulonglong2 ewv = *(const ulonglong2*)(pw + o * 8176);
#pragma unroll
                for (int i = 0; i < 4; i++) {
                    fma2(acc[o][i], ewv.x, exv[i].x);
                    fma2(acc[o][i], ewv.y, exv[i].y);
                }
            }
        }
    }

    // ---- reduction ----
    float s[8][4];
#pragma unroll
    for (int o = 0; o < 8; o++)
#pragma unroll
        for (int i = 0; i < 4; i++) {
            float2 p = unpack2(acc[o][i]);
            float v = p.x + p.y;
            v += __shfl_xor_sync(0xffffffffu, v, 1);
            v += __shfl_xor_sync(0xffffffffu, v, 2);
            s[o][i] = v;
        }

    __shared__ float red[64][36];
    if (cq == 0) {
        int contrib = warp * 8 + rp;
#pragma unroll
        for (int o = 0; o < 8; o++) {
            float4 v4 = make_float4(s[o][0], s[o][1], s[o][2], s[o][3]);
            *(float4*)&red[contrib][o * 4] = v4;
        }
    }
    __syncthreads();

    if (t < 128) {
        int o   = t >> 4;
        int b   = t & 15;
        int bqq = b >> 2;
        int bl_ = b & 3;
        float v = 0.f;
#pragma unroll
        for (int k2 = 0; k2 < 2; k2++)
#pragma unroll
            for (int r = 0; r < 8; r++)
                v += red[(k2 * 4 + bqq) * 8 + r][o * 4 + bl_];
        int og = o0 + o;
        if (og < O1_) {
            float h = v + b1[og];
            h = (h > 0.f) ? h : expm1f(h);
            g_h1b[b * 1024 + og] = h;
        } else {
            g_h1b[b * 1024 + og] = 0.f;   // og == 1023 masked slot -> 0
        }
    }
}

// ---------------------------------------------------------------------------
// K2: 384 blocks x 256 threads, PDL secondary.
// PRE-sync (h1-independent): load x float4, compute r0 = (x - mm)*sc + beta.
// cudaGridDependencySynchronize()
// POST-sync: coalesced gate dot (float4 over uL/uS/h1b), r = r0 + g*sc, store.
// ---------------------------------------------------------------------------
__global__ void __launch_bounds__(256) k_out(
        const float* __restrict__ x,    const float* __restrict__ gamma,
        const float* __restrict__ beta, const float* __restrict__ mm,
        const float* __restrict__ mv,   float* __restrict__ out) {
    const int t    = threadIdx.x;
    const int bid  = blockIdx.x;
    const int lane = t & 31;
    const int warp = t >> 5;

    // ---------- PRE-sync ----------
    const int b0  = (bid * 64) / (L_ + 1);          // batches this block spans
    const int b1i = (b0 + 1 < B_) ? b0 + 1 : b0;

    int i4   = bid * 256 + t;            // [0, 98304)
    int cq   = i4 & 3;
    int c0   = 4 * cq;
    int rest = i4 >> 2;
    int l    = rest % (L_ + 1);
    int b    = rest / (L_ + 1);

    float4 xv = make_float4(0.f, 0.f, 0.f, 0.f);
    if (l < L_) xv = *(const float4*)(x + (b * L_ + l) * 16 + c0);

    float4 sc;
    sc.x = rsqrtf(mv[c0 + 0] + EPS_) * gamma[c0 + 0];
    sc.y = rsqrtf(mv[c0 + 1] + EPS_) * gamma[c0 + 1];
    sc.z = rsqrtf(mv[c0 + 2] + EPS_) * gamma[c0 + 2];
    sc.w = rsqrtf(mv[c0 + 3] + EPS_) * gamma[c0 + 3];
    float4 r0;
    r0.x = (xv.x - mm[c0 + 0]) * sc.x + beta[c0 + 0];
    r0.y = (xv.y - mm[c0 + 1]) * sc.y + beta[c0 + 1];
    r0.z = (xv.z - mm[c0 + 2]) * sc.z + beta[c0 + 2];
    r0.w = (xv.w - mm[c0 + 3]) * sc.w + beta[c0 + 3];

    // ---------- wait for stage1/prep ----------
    cudaGridDependencySynchronize();

    // ---------- gate dot: fully coalesced float4 over j = 4t..4t+3 ----------
    float4 ul = ((const float4*)g_uL)[t];
    float4 us = ((const float4*)g_uS)[t];
    float4 h0 = ((const float4*)(g_h1b + b0 * 1024))[t];
    float4 h1v = ((const float4*)(g_h1b + b1i * 1024))[t];

    float aL0 = ul.x * h0.x + ul.y * h0.y + ul.z * h0.z + ul.w * h0.w;
    float aS0 = us.x * h0.x + us.y * h0.y + us.z * h0.z + us.w * h0.w;
    float aL1 = ul.x * h1v.x + ul.y * h1v.y + ul.z * h1v.z + ul.w * h1v.w;
    float aS1 = us.x * h1v.x + us.y * h1v.y + us.z * h1v.z + us.w * h1v.w;

#pragma unroll
    for (int off = 16; off; off >>= 1) {
        aL0 += __shfl_down_sync(0xffffffffu, aL0, off);
        aS0 += __shfl_down_sync(0xffffffffu, aS0, off);
        aL1 += __shfl_down_sync(0xffffffffu, aL1, off);
        aS1 += __shfl_down_sync(0xffffffffu, aS1, off);
    }
    __shared__ float rr[8][4];
    __shared__ float s_gate[2];
    if (lane == 0) {
        rr[warp][0] = aL0; rr[warp][1] = aS0;
        rr[warp][2] = aL1; rr[warp][3] = aS1;
    }
    __syncthreads();
    if (t == 0) {
        float AL0 = g_const[0], AS0 = g_const[1];
        float AL1 = g_const[0], AS1 = g_const[1];
#pragma unroll
        for (int w = 0; w < 8; w++) {
            AL0 += rr[w][0]; AS0 += rr[w][1];
            AL1 += rr[w][2]; AS1 += rr[w][3];
        }
        s_gate[0] = AL0 * (1.f / (1.f + expf(-AS0)));
        s_gate[1] = AL1 * (1.f / (1.f + expf(-AS1)));
    }
    __syncthreads();

    // ---------- finish: r = r0 + g*sc ----------
    float g = s_gate[b - b0];
    float4 r;
    r.x = r0.x + g * sc.x;
    r.y = r0.y + g * sc.y;
    r.z = r0.z + g * sc.z;
    r.w = r0.w + g * sc.w;
    ((float4*)out)[i4] = r;
}

// ---------------------------------------------------------------------------
extern "C" void kernel_launch(void* const* d_in, const int* in_sizes, int n_in,
                              void* d_out, int out_size) {
    const float* x     = (const float*)d_in[0];
    const float* W1    = (const float*)d_in[1];
    const float* b1    = (const float*)d_in[2];
    const float* W2    = (const float*)d_in[3];
    const float* b2    = (const float*)d_in[4];
    const float* Wl    = (const float*)d_in[5];
    const float* bl    = (const float*)d_in[6];
    const float* Ws    = (const float*)d_in[7];
    const float* bs    = (const float*)d_in[8];
    const float* gamma = (const float*)d_in[9];
    const float* beta  = (const float*)d_in[10];
    const float* mm    = (const float*)d_in[11];
    const float* mv    = (const float*)d_in[12];
    float* out = (float*)d_out;

    k_stage1_prep<<<144, 256>>>(x, W1, b1, W2, b2, Wl, bl, Ws, bs);

    // PDL: k_out launches overlapped; it self-synchronizes via
    // cudaGridDependencySynchronize() before touching h1/u.
    cudaLaunchConfig_t cfg = {};
    cfg.gridDim  = dim3(384, 1, 1);
    cfg.blockDim = dim3(256, 1, 1);
    cfg.dynamicSmemBytes = 0;
    cfg.stream = 0;
    cudaLaunchAttribute attrs[1];
    attrs[0].id = cudaLaunchAttributeProgrammaticStreamSerialization;
    attrs[0].val.programmaticStreamSerializationAllowed = 1;
    cfg.attrs = attrs;
    cfg.numAttrs = 1;
    cudaLaunchKernelEx(&cfg, k_out, x, gamma, beta, mm, mv, out);
}

// round 15
// speedup vs baseline: 1.4747x; 1.4747x over previous
#include <cuda_runtime.h>
#include <math.h>

#define B_   16
#define L_   1534
#define C_   16
#define SZ_  512
#define O1_  1023
#define O2_  512
#define EPS_ 1e-3f

__device__ __align__(16) float g_h1b[B_ * 1024];   // h1: [b][o] (o=1023 slot = 0)
__device__ __align__(16) float g_uL[1024];   // uL[j] = sum_o Wl[o]*W2[o][j-o]
__device__ __align__(16) float g_uS[1024];
__device__ float g_const[2];                 // constL, constS

__device__ __forceinline__ void fma2(unsigned long long& d,
                                     unsigned long long a,
                                     unsigned long long b) {
    asm("fma.rn.f32x2 %0, %1, %2, %0;" : "+l"(d) : "l"(a), "l"(b));
}
__device__ __forceinline__ float2 unpack2(unsigned long long v) {
    float2 r;
    asm("mov.b64 {%0, %1}, %2;" : "=f"(r.x), "=f"(r.y) : "l"(v));
    return r;
}

// ---------------------------------------------------------------------------
// K1: 144 blocks.
//   bid 0..127 : stage1 (proven R6 core): h1 = elu(local matmul), stored
//                as [b][o] (coalesced for K2's gate dot); o=1023 slot zeroed.
//   bid 128..143: gate-weight precompute uL/uS (weights-only, hidden under
//                stage1; 144 blocks = one wave on 148 SMs).
// ---------------------------------------------------------------------------
__global__ void __launch_bounds__(256) k_stage1_prep(
        const float* __restrict__ x,  const float* __restrict__ W1,
        const float* __restrict__ b1, const float* __restrict__ W2,
        const float* __restrict__ b2, const float* __restrict__ Wl,
        const float* __restrict__ bl, const float* __restrict__ Ws,
        const float* __restrict__ bs) {
    const int t    = threadIdx.x;
    const int bid  = blockIdx.x;
    const int lane = t & 31;
    const int warp = t >> 5;

    if (bid >= 128) {
        // ================= PREP: u vectors =================
        const int ch = bid - 128;        // 0..15
        const int j0 = ch * 64;
        const int jl = t & 63;
        const int op = t >> 6;
        const int j  = j0 + jl;

        float aL = 0.f, aS = 0.f;
        for (int o = op; o < SZ_; o += 4) {
            int s = j - o;
            if (0 <= s && s < SZ_) {
                float w = W2[o * SZ_ + s];
                aL = fmaf(Wl[o], w, aL);
                aS = fmaf(Ws[o], w, aS);
            }
        }
        __shared__ float sL[4][64], sS[4][64];
        sL[op][jl] = aL;
        sS[op][jl] = aS;
        __syncthreads();
        if (t < 64) {
            g_uL[j0 + t] = sL[0][t] + sL[1][t] + sL[2][t] + sL[3][t];
            g_uS[j0 + t] = sS[0][t] + sS[1][t] + sS[2][t] + sS[3][t];
        }
        if (ch == 0 && warp == 3) {
            float cL = 0.f, cS = 0.f;
            for (int o = lane; o < SZ_; o += 32) {
                float bv = b2[o];
                cL = fmaf(Wl[o], bv, cL);
                cS = fmaf(Ws[o], bv, cS);
            }
#pragma unroll
            for (int off = 16; off; off >>= 1) {
                cL += __shfl_down_sync(0xffffffffu, cL, off);
                cS += __shfl_down_sync(0xffffffffu, cS, off);
            }
            if (lane == 0) {
                g_const[0] = bl[0] + cL;
                g_const[1] = bs[0] + cS;
            }
        }
        return;
    }

    // ================= STAGE 1 (proven R6 core) =================
    const int cq   = lane & 3;
    const int rp   = lane >> 2;
    const int bq   = warp & 3;
    const int kh   = warp >> 2;
    const int o0   = bid * 8;
    const bool full = (o0 + 8 <= O1_);

    unsigned long long acc[8][4];
#pragma unroll
    for (int o = 0; o < 8; o++)
#pragma unroll
        for (int i = 0; i < 4; i++) acc[o][i] = 0ull;

    const int k_begin = kh ? 32 : 0;

    const float* px[4];
#pragma unroll
    for (int i = 0; i < 4; i++)
        px[i] = x + ((4 * bq + i) * L_ + o0 + rp) * 16 + 4 * cq + k_begin * 128;
    const float* pw = W1 + o0 * (SZ_ * C_) + rp * 16 + 4 * cq + k_begin * 128;

    // ---- prologue (kh=0 only), k=0, d=rp: valid o <= rp ----
    if (kh == 0) {
        ulonglong2 xv[4];
#pragma unroll
        for (int i = 0; i < 4; i++) xv[i] = *(const ulonglong2*)px[i];
#pragma unroll
        for (int o = 0; o < 8; o++) {
            if (o <= rp && (full || o0 + o < O1_)) {
                ulonglong2 wv = *(const ulonglong2*)(pw + o * 8176);
#pragma unroll
                for (int i = 0; i < 4; i++) {
                    fma2(acc[o][i], wv.x, xv[i].x);
                    fma2(acc[o][i], wv.y, xv[i].y);
                }
            }
        }
#pragma unroll
        for (int i = 0; i < 4; i++) px[i] += 128;
        pw += 128;
    }

    // ---- interior, software-pipelined double buffer ----
    const int kcount = kh ? 32 : 31;

    ulonglong2 xv[2][4], wv[2][8];
#pragma unroll
    for (int i = 0; i < 4; i++) xv[0][i] = *(const ulonglong2*)px[i];
#pragma unroll
    for (int o = 0; o < 8; o++) wv[0][o] = *(const ulonglong2*)(pw + o * 8176);
#pragma unroll
    for (int i = 0; i < 4; i++) px[i] += 128;
    pw += 128;

    if (full) {
#pragma unroll 2
        for (int k = 0; k < kcount; k++) {
            const int cur = k & 1, nxt = cur ^ 1;
            if (k + 1 < kcount) {
#pragma unroll
                for (int i = 0; i < 4; i++) xv[nxt][i] = *(const ulonglong2*)px[i];
#pragma unroll
                for (int o = 0; o < 8; o++) wv[nxt][o] = *(const ulonglong2*)(pw + o * 8176);
#pragma unroll
                for (int i = 0; i < 4; i++) px[i] += 128;
                pw += 128;
            }
#pragma unroll
            for (int o = 0; o < 8; o++)
#pragma unroll
                for (int i = 0; i < 4; i++) {
                    fma2(acc[o][i], wv[cur][o].x, xv[cur][i].x);
                    fma2(acc[o][i], wv[cur][o].y, xv[cur][i].y);
                }
        }
    } else {
#pragma unroll 2
        for (int k = 0; k < kcount; k++) {
            const int cur = k & 1, nxt = cur ^ 1;
            if (k + 1 < kcount) {
#pragma unroll
                for (int i = 0; i < 4; i++) xv[nxt][i] = *(const ulonglong2*)px[i];
#pragma unroll
                for (int o = 0; o < 8; o++)
                    if (o0 + o < O1_) wv[nxt][o] = *(const ulonglong2*)(pw + o * 8176);
#pragma unroll
                for (int i = 0; i < 4; i++) px[i] += 128;
                pw += 128;
            }
#pragma unroll
            for (int o = 0; o < 8; o++) {
                if (o0 + o < O1_) {
#pragma unroll
                    for (int i = 0; i < 4; i++) {
                        fma2(acc[o][i], wv[cur][o].x, xv[cur][i].x);
                        fma2(acc[o][i], wv[cur][o].y, xv[cur][i].y);
                    }
                }
            }
        }
    }

    // ---- epilogue (kh=1 only), k=64, d=512+rp: valid o > rp ----
    if (kh == 1) {
        int row = o0 + 512 + rp;
        if (row > L_ - 1) row = L_ - 1;     // clamped slots only hit masked o's
        ulonglong2 exv[4];
#pragma unroll
        for (int i = 0; i < 4; i++)
            exv[i] = *(const ulonglong2*)(x + ((4 * bq + i) * L_ + row) * 16 + 4 * cq);
#pragma unroll
        for (int o = 0; o < 8; o++) {
            if (o > rp && (full || o0 + o < O1_)) {
                ulonglong2 ewv = *(const ulonglong2*)(pw + o * 8176);
#pragma unroll
                for (int i = 0; i < 4; i++) {
                    fma2(acc[o][i], ewv.x, exv[i].x);
                    fma2(acc[o][i], ewv.y, exv[i].y);
                }
            }
        }
    }

    // ---- reduction ----
    float s[8][4];
#pragma unroll
    for (int o = 0; o < 8; o++)
#pragma unroll
        for (int i = 0; i < 4; i++) {
            float2 p = unpack2(acc[o][i]);
            float v = p.x + p.y;
            v += __shfl_xor_sync(0xffffffffu, v, 1);
            v += __shfl_xor_sync(0xffffffffu, v, 2);
            s[o][i] = v;
        }

    __shared__ float red[64][36];
    if (cq == 0) {
        int contrib = warp * 8 + rp;
#pragma unroll
        for (int o = 0; o < 8; o++) {
            float4 v4 = make_float4(s[o][0], s[o][1], s[o][2], s[o][3]);
            *(float4*)&red[contrib][o * 4] = v4;
        }
    }
    __syncthreads();

    if (t < 128) {
        int o   = t >> 4;
        int b   = t & 15;
        int bqq = b >> 2;
        int bl_ = b & 3;
        float v = 0.f;
#pragma unroll
        for (int k2 = 0; k2 < 2; k2++)
#pragma unroll
            for (int r = 0; r < 8; r++)
                v += red[(k2 * 4 + bqq) * 8 + r][o * 4 + bl_];
        int og = o0 + o;
        if (og < O1_) {
            float h = v + b1[og];
            h = (h > 0.f) ? h : expm1f(h);
            g_h1b[b * 1024 + og] = h;
        } else {
            g_h1b[b * 1024 + og] = 0.f;   // og == 1023 masked slot -> 0
        }
    }
}

// ---------------------------------------------------------------------------
// K2: 384 blocks x 256 threads, PLAIN launch (stream-ordered; no PDL — four
// rounds of evidence show waiting CTAs of any flavor cost 5-10us here).
// Gate dot is fully coalesced float4 over uL/uS/h1b[b][o]; then one float4
// of output per thread.
// ---------------------------------------------------------------------------
__global__ void __launch_bounds__(256) k_out(
        const float* __restrict__ x,    const float* __restrict__ gamma,
        const float* __restrict__ beta, const float* __restrict__ mm,
        const float* __restrict__ mv,   float* __restrict__ out) {
    const int t    = threadIdx.x;
    const int bid  = blockIdx.x;
    const int lane = t & 31;
    const int warp = t >> 5;

    // batches this block touches: rest in [bid*64, bid*64+64)
    const int b0  = (bid * 64) / (L_ + 1);
    const int b1i = (b0 + 1 < B_) ? b0 + 1 : b0;

    // ---- gate dot: coalesced float4 over j = 4t..4t+3 ----
    float4 ul  = ((const float4*)g_uL)[t];
    float4 us  = ((const float4*)g_uS)[t];
    float4 h0  = ((const float4*)(g_h1b + b0 * 1024))[t];
    float4 h1v = ((const float4*)(g_h1b + b1i * 1024))[t];

    float aL0 = ul.x * h0.x + ul.y * h0.y + ul.z * h0.z + ul.w * h0.w;
    float aS0 = us.x * h0.x + us.y * h0.y + us.z * h0.z + us.w * h0.w;
    float aL1 = ul.x * h1v.x + ul.y * h1v.y + ul.z * h1v.z + ul.w * h1v.w;
    float aS1 = us.x * h1v.x + us.y * h1v.y + us.z * h1v.z + us.w * h1v.w;

#pragma unroll
    for (int off = 16; off; off >>= 1) {
        aL0 += __shfl_down_sync(0xffffffffu, aL0, off);
        aS0 += __shfl_down_sync(0xffffffffu, aS0, off);
        aL1 += __shfl_down_sync(0xffffffffu, aL1, off);
        aS1 += __shfl_down_sync(0xffffffffu, aS1, off);
    }
    __shared__ float rr[8][4];
    __shared__ float s_gate[2];
    if (lane == 0) {
        rr[warp][0] = aL0; rr[warp][1] = aS0;
        rr[warp][2] = aL1; rr[warp][3] = aS1;
    }
    __syncthreads();
    if (t == 0) {
        float AL0 = g_const[0], AS0 = g_const[1];
        float AL1 = g_const[0], AS1 = g_const[1];
#pragma unroll
        for (int w = 0; w < 8; w++) {
            AL0 += rr[w][0]; AS0 += rr[w][1];
            AL1 += rr[w][2]; AS1 += rr[w][3];
        }
        s_gate[0] = AL0 * (1.f / (1.f + expf(-AS0)));
        s_gate[1] = AL1 * (1.f / (1.f + expf(-AS1)));
    }
    __syncthreads();

    // ---- output: one float4 per thread ----
    int i4   = bid * 256 + t;            // [0, 98304)
    int cq   = i4 & 3;
    int c0   = 4 * cq;
    int rest = i4 >> 2;
    int l    = rest % (L_ + 1);
    int b    = rest / (L_ + 1);

    float4 xv = make_float4(0.f, 0.f, 0.f, 0.f);
    if (l < L_) xv = *(const float4*)(x + (b * L_ + l) * 16 + c0);

    float g = s_gate[b - b0];
    float sx = rsqrtf(mv[c0 + 0] + EPS_) * gamma[c0 + 0];
    float sy = rsqrtf(mv[c0 + 1] + EPS_) * gamma[c0 + 1];
    float sz = rsqrtf(mv[c0 + 2] + EPS_) * gamma[c0 + 2];
    float sw = rsqrtf(mv[c0 + 3] + EPS_) * gamma[c0 + 3];
    float4 r;
    r.x = (xv.x + g - mm[c0 + 0]) * sx + beta[c0 + 0];
    r.y = (xv.y + g - mm[c0 + 1]) * sy + beta[c0 + 1];
    r.z = (xv.z + g - mm[c0 + 2]) * sz + beta[c0 + 2];
    r.w = (xv.w + g - mm[c0 + 3]) * sw + beta[c0 + 3];
    ((float4*)out)[i4] = r;
}

// ---------------------------------------------------------------------------
extern "C" void kernel_launch(void* const* d_in, const int* in_sizes, int n_in,
                              void* d_out, int out_size) {
    const float* x     = (const float*)d_in[0];
    const float* W1    = (const float*)d_in[1];
    const float* b1    = (const float*)d_in[2];
    const float* W2    = (const float*)d_in[3];
    const float* b2    = (const float*)d_in[4];
    const float* Wl    = (const float*)d_in[5];
    const float* bl    = (const float*)d_in[6];
    const float* Ws    = (const float*)d_in[7];
    const float* bs    = (const float*)d_in[8];
    const float* gamma = (const float*)d_in[9];
    const float* beta  = (const float*)d_in[10];
    const float* mm    = (const float*)d_in[11];
    const float* mv    = (const float*)d_in[12];
    float* out = (float*)d_out;

    k_stage1_prep<<<144, 256>>>(x, W1, b1, W2, b2, Wl, bl, Ws, bs);
    k_out<<<384, 256>>>(x, gamma, beta, mm, mv, out);
}